// round 1
// baseline (speedup 1.0000x reference)
#include <cuda_runtime.h>
#include <math.h>

// Problem constants
#define NBATCH 8
#define LSEQ   2048
#define CDIM   256
#define DDIM   32
#define MROWS  (NBATCH * LSEQ)   // 16384

// ---------------------------------------------------------------------------
// Device scratch (static globals; no runtime allocation allowed)
// ---------------------------------------------------------------------------
__device__ float g_ecg[MROWS * CDIM];          // 16 MB
__device__ float g_pcg[MROWS * CDIM];          // 16 MB
__device__ float g_Qs[4][MROWS * DDIM];        //  8 MB
__device__ float g_Ks[4][MROWS * DDIM];        //  8 MB
__device__ float g_Vs[4][MROWS * CDIM];        // 64 MB

// ---------------------------------------------------------------------------
// Split x[B,L,C,2] into two contiguous streams (coalesced float2 reads)
// ---------------------------------------------------------------------------
__global__ void split_kernel(const float2* __restrict__ x,
                             float* __restrict__ e, float* __restrict__ p) {
    int i = blockIdx.x * blockDim.x + threadIdx.x;
    if (i < MROWS * CDIM) {
        float2 v = x[i];
        e[i] = v.x;
        p[i] = v.y;
    }
}

// ---------------------------------------------------------------------------
// Projection GEMM: Y[M,N] = X[M,256] @ W[256,N]
// Block tile: 64 rows x TN cols, K-chunks of 32. 256 threads.
// Thread tile: 4 rows x RN cols (cols strided by 16 -> conflict-free LDS).
// If gate != nullptr and *gate == 0, skip entirely (output never read).
// ---------------------------------------------------------------------------
template<int TN, int RN>
__global__ __launch_bounds__(256)
void proj_kernel(const float* __restrict__ X, const float* __restrict__ W,
                 float* __restrict__ Y, int N, const float* __restrict__ gate) {
    if (gate && gate[0] == 0.0f) return;

    __shared__ float Xs[64][33];
    __shared__ float Ws[32][TN];

    const int tid = threadIdx.x;
    const int ty  = tid >> 4;        // 0..15 -> row group
    const int tx  = tid & 15;        // 0..15 -> col lane
    const int m0  = blockIdx.y * 64;
    const int n0  = blockIdx.x * TN;

    float acc[4][RN];
#pragma unroll
    for (int r = 0; r < 4; r++)
#pragma unroll
        for (int n = 0; n < RN; n++) acc[r][n] = 0.0f;

    for (int kc = 0; kc < CDIM; kc += 32) {
        // X tile: 64x32, coalesced
#pragma unroll
        for (int t = 0; t < 8; t++) {
            int e = tid + t * 256;
            int r = e >> 5, k = e & 31;
            Xs[r][k] = X[(m0 + r) * CDIM + kc + k];
        }
        // W tile: 32xTN, coalesced
#pragma unroll
        for (int t = 0; t < (32 * TN) / 256; t++) {
            int e = tid + t * 256;
            int k = e / TN, c = e % TN;
            Ws[k][c] = W[(kc + k) * N + n0 + c];
        }
        __syncthreads();

#pragma unroll
        for (int k = 0; k < 32; k++) {
            float a[4], b[RN];
#pragma unroll
            for (int r = 0; r < 4; r++) a[r] = Xs[ty * 4 + r][k];
#pragma unroll
            for (int n = 0; n < RN; n++) b[n] = Ws[k][tx + 16 * n];
#pragma unroll
            for (int r = 0; r < 4; r++)
#pragma unroll
                for (int n = 0; n < RN; n++) acc[r][n] = fmaf(a[r], b[n], acc[r][n]);
        }
        __syncthreads();
    }

#pragma unroll
    for (int r = 0; r < 4; r++) {
        int row = m0 + ty * 4 + r;
#pragma unroll
        for (int n = 0; n < RN; n++)
            Y[row * N + n0 + tx + 16 * n] = acc[r][n];
    }
}

// ---------------------------------------------------------------------------
// Flash attention (fp32, online softmax).
// Q tile 64 x 32, K tiles 64 x 32, V tiles 64 x 256.
// 256 threads: (ty=tid/16, tx=tid%16). Thread owns rows ty*4..+3,
// cols {tx + 16n : n=0..15} -> 4x16 register accumulator.
// Scores stored transposed Ps[j][i] with row pitch 65 (odd -> conflict-free).
// ---------------------------------------------------------------------------
struct AttnSmem {
    float Qs[64][33];
    float Ks[64][33];
    float Vs[64][256];
    float Ps[64][65];
    float mrow[64];
    float lrow[64];
    float resc[64];
    float red[4][64];
};

extern __shared__ char attn_smem_raw[];

__global__ __launch_bounds__(256, 2)
void attn_kernel(const float* __restrict__ Qg, const float* __restrict__ Kg,
                 const float* __restrict__ Vg, float* __restrict__ out,
                 int chanOff, const float* __restrict__ gate, int addMode) {
    if (gate && gate[0] == 0.0f) return;           // intra path gated off
    const float gv = gate ? gate[0] : 1.0f;

    AttnSmem& s = *reinterpret_cast<AttnSmem*>(attn_smem_raw);
    const int tid = threadIdx.x;
    const int ty  = tid >> 4;
    const int tx  = tid & 15;
    const int b   = blockIdx.y;
    const int qt  = blockIdx.x;

    const float* Qb = Qg + (size_t)(b * LSEQ + qt * 64) * DDIM;
    const float* Kb = Kg + (size_t)b * LSEQ * DDIM;
    const float* Vb = Vg + (size_t)b * LSEQ * CDIM;
    const float inv_scale = rsqrtf((float)DDIM);

    // Load Q (pre-scaled by 1/sqrt(D))
#pragma unroll
    for (int t = 0; t < 8; t++) {
        int e = tid + t * 256;
        int r = e >> 5, d = e & 31;
        s.Qs[r][d] = Qb[e] * inv_scale;
    }
    if (tid < 64) { s.mrow[tid] = -3.402823466e38f; s.lrow[tid] = 0.0f; }

    float acc[4][16];
#pragma unroll
    for (int r = 0; r < 4; r++)
#pragma unroll
        for (int n = 0; n < 16; n++) acc[r][n] = 0.0f;

    __syncthreads();

    for (int kt = 0; kt < LSEQ / 64; kt++) {
        const float*  Kt = Kb + (size_t)kt * 64 * DDIM;
        const float4* Vt = (const float4*)(Vb + (size_t)kt * 64 * CDIM);

        // K tile 64x32
#pragma unroll
        for (int t = 0; t < 8; t++) {
            int e = tid + t * 256;
            int r = e >> 5, d = e & 31;
            s.Ks[r][d] = Kt[e];
        }
        // V tile 64x256 as float4 (contiguous in smem)
#pragma unroll
        for (int t = 0; t < 16; t++) {
            int e = tid + t * 256;
            ((float4*)&s.Vs[0][0])[e] = Vt[e];
        }
        __syncthreads();

        // S = Q K^T ; thread: rows ty*4..+3, keys {tx+16k}
        float sr[4][4];
#pragma unroll
        for (int r = 0; r < 4; r++)
#pragma unroll
            for (int k = 0; k < 4; k++) sr[r][k] = 0.0f;
#pragma unroll
        for (int d = 0; d < 32; d++) {
            float a[4], bb[4];
#pragma unroll
            for (int r = 0; r < 4; r++) a[r] = s.Qs[ty * 4 + r][d];
#pragma unroll
            for (int k = 0; k < 4; k++) bb[k] = s.Ks[tx + 16 * k][d];
#pragma unroll
            for (int r = 0; r < 4; r++)
#pragma unroll
                for (int k = 0; k < 4; k++) sr[r][k] = fmaf(a[r], bb[k], sr[r][k]);
        }
        // Store transposed: Ps[j][i]
#pragma unroll
        for (int r = 0; r < 4; r++)
#pragma unroll
            for (int k = 0; k < 4; k++)
                s.Ps[tx + 16 * k][ty * 4 + r] = sr[r][k];
        __syncthreads();

        // Row max (per query i): 4 partials over j
        const int ii = tid & 63, qq = tid >> 6;
        {
            float pm = -3.402823466e38f;
#pragma unroll
            for (int jj = 0; jj < 16; jj++)
                pm = fmaxf(pm, s.Ps[qq * 16 + jj][ii]);
            s.red[qq][ii] = pm;
        }
        __syncthreads();
        if (tid < 64) {
            float tm = fmaxf(fmaxf(s.red[0][tid], s.red[1][tid]),
                             fmaxf(s.red[2][tid], s.red[3][tid]));
            float mo = s.mrow[tid];
            float mn = fmaxf(mo, tm);
            s.resc[tid] = __expf(mo - mn);
            s.mrow[tid] = mn;
        }
        __syncthreads();

        // exp + partial row sums (in-place on Ps)
        {
            const float mloc = s.mrow[ii];
            float psum = 0.0f;
#pragma unroll
            for (int jj = 0; jj < 16; jj++) {
                float pv = __expf(s.Ps[qq * 16 + jj][ii] - mloc);
                s.Ps[qq * 16 + jj][ii] = pv;
                psum += pv;
            }
            s.red[qq][ii] = psum;
        }
        __syncthreads();
        if (tid < 64)
            s.lrow[tid] = s.lrow[tid] * s.resc[tid] +
                          s.red[0][tid] + s.red[1][tid] + s.red[2][tid] + s.red[3][tid];

        // Rescale accumulator
#pragma unroll
        for (int r = 0; r < 4; r++) {
            float f = s.resc[ty * 4 + r];
#pragma unroll
            for (int n = 0; n < 16; n++) acc[r][n] *= f;
        }

        // PV accumulate: acc[r][n] += P[i][j] * V[j][c]
#pragma unroll 2
        for (int j = 0; j < 64; j++) {
            float p[4];
#pragma unroll
            for (int r = 0; r < 4; r++) p[r] = s.Ps[j][ty * 4 + r];
#pragma unroll
            for (int n = 0; n < 16; n++) {
                float v = s.Vs[j][tx + 16 * n];
#pragma unroll
                for (int r = 0; r < 4; r++) acc[r][n] = fmaf(p[r], v, acc[r][n]);
            }
        }
        __syncthreads();
    }

    // Epilogue
#pragma unroll
    for (int r = 0; r < 4; r++) {
        int i = ty * 4 + r;
        float inv_l = 1.0f / s.lrow[i];
        size_t row = (size_t)(b * LSEQ + qt * 64 + i);
        float* orow = out + row * (2 * CDIM) + chanOff;
#pragma unroll
        for (int n = 0; n < 16; n++) {
            float v = acc[r][n] * inv_l;
            int c = tx + 16 * n;
            if (addMode) orow[c] += gv * v;
            else         orow[c] = v;
        }
    }
}

// ---------------------------------------------------------------------------
// Launcher
// Inputs: d_in[0]=x, d_in[1..12]=w1..w12, d_in[13]=alpha, d_in[14]=gamma
// Output: float32 [B, L, 512]
// ---------------------------------------------------------------------------
extern "C" void kernel_launch(void* const* d_in, const int* in_sizes, int n_in,
                              void* d_out, int out_size) {
    const float* x     = (const float*)d_in[0];
    const float* w[13];
    for (int i = 1; i <= 12; i++) w[i] = (const float*)d_in[i];
    const float* alpha = (const float*)d_in[13];
    const float* gamma = (const float*)d_in[14];
    float* out = (float*)d_out;

    float *ecg, *pcg, *Qb, *Kb, *Vb;
    cudaGetSymbolAddress((void**)&ecg, g_ecg);
    cudaGetSymbolAddress((void**)&pcg, g_pcg);
    cudaGetSymbolAddress((void**)&Qb,  g_Qs);
    cudaGetSymbolAddress((void**)&Kb,  g_Ks);
    cudaGetSymbolAddress((void**)&Vb,  g_Vs);

    auto Q = [&](int a) { return Qb + (size_t)a * MROWS * DDIM; };
    auto K = [&](int a) { return Kb + (size_t)a * MROWS * DDIM; };
    auto V = [&](int a) { return Vb + (size_t)a * MROWS * CDIM; };

    cudaFuncSetAttribute(attn_kernel,
                         cudaFuncAttributeMaxDynamicSharedMemorySize,
                         (int)sizeof(AttnSmem));

    // 1) de-interleave x
    {
        int tot = MROWS * CDIM;
        split_kernel<<<(tot + 255) / 256, 256>>>((const float2*)x, ecg, pcg);
    }

    // 2) projections
    dim3 gD(1, MROWS / 64);                 // N = 32
    dim3 gC(CDIM / 128, MROWS / 64);        // N = 256
    // inter: attn0 = ecg_inter (Q=ecg@w4, K=pcg@w5, V=pcg@w6)
    proj_kernel<32, 2><<<gD, 256>>>(ecg, w[4],  Q(0), DDIM, nullptr);
    proj_kernel<32, 2><<<gD, 256>>>(pcg, w[5],  K(0), DDIM, nullptr);
    proj_kernel<128, 8><<<gC, 256>>>(pcg, w[6],  V(0), CDIM, nullptr);
    // inter: attn1 = pcg_inter (Q=pcg@w10, K=ecg@w11, V=ecg@w12)
    proj_kernel<32, 2><<<gD, 256>>>(pcg, w[10], Q(1), DDIM, nullptr);
    proj_kernel<32, 2><<<gD, 256>>>(ecg, w[11], K(1), DDIM, nullptr);
    proj_kernel<128, 8><<<gC, 256>>>(ecg, w[12], V(1), CDIM, nullptr);
    // intra (gated by alpha): attn2 = ecg_intra (w1, w2, w3)
    proj_kernel<32, 2><<<gD, 256>>>(ecg, w[1],  Q(2), DDIM, alpha);
    proj_kernel<32, 2><<<gD, 256>>>(ecg, w[2],  K(2), DDIM, alpha);
    proj_kernel<128, 8><<<gC, 256>>>(ecg, w[3],  V(2), CDIM, alpha);
    // intra (gated by gamma): attn3 = pcg_intra (w7, w8, w9)
    proj_kernel<32, 2><<<gD, 256>>>(pcg, w[7],  Q(3), DDIM, gamma);
    proj_kernel<32, 2><<<gD, 256>>>(pcg, w[8],  K(3), DDIM, gamma);
    proj_kernel<128, 8><<<gC, 256>>>(pcg, w[9],  V(3), CDIM, gamma);

    // 3) attentions
    dim3 ga(LSEQ / 64, NBATCH);
    size_t smem = sizeof(AttnSmem);
    attn_kernel<<<ga, 256, smem>>>(Q(0), K(0), V(0), out, 0,    nullptr, 0);
    attn_kernel<<<ga, 256, smem>>>(Q(1), K(1), V(1), out, CDIM, nullptr, 0);
    attn_kernel<<<ga, 256, smem>>>(Q(2), K(2), V(2), out, 0,    alpha,   1);
    attn_kernel<<<ga, 256, smem>>>(Q(3), K(3), V(3), out, CDIM, gamma,   1);
}

// round 2
// speedup vs baseline: 1.6722x; 1.6722x over previous
#include <cuda_runtime.h>
#include <math.h>

#define NBATCH 8
#define LSEQ   2048
#define CDIM   256
#define DDIM   32
#define MROWS  (NBATCH * LSEQ)   // 16384
#define TQ     128
#define TK     64

// ---------------------------------------------------------------------------
// Device scratch
// ---------------------------------------------------------------------------
__device__ float g_ecg[MROWS * CDIM];
__device__ float g_pcg[MROWS * CDIM];
__device__ float g_Qs[4][MROWS * DDIM];
__device__ float g_Ks[4][MROWS * DDIM];
__device__ float g_Vs[4][MROWS * CDIM];

// ---------------------------------------------------------------------------
// Helpers: tf32 convert (round-to-nearest) and m16n8k8 tf32 mma
// ---------------------------------------------------------------------------
__device__ __forceinline__ unsigned cvt_tf32(float f) {
    unsigned u; asm("cvt.rna.tf32.f32 %0, %1;" : "=r"(u) : "f"(f)); return u;
}
__device__ __forceinline__ float cvt_tf32f(float f) {
    return __uint_as_float(cvt_tf32(f));
}
__device__ __forceinline__ unsigned fasu(float f) { return __float_as_uint(f); }

__device__ __forceinline__ void mma_tf32(float& c0, float& c1, float& c2, float& c3,
                                         unsigned a0, unsigned a1, unsigned a2, unsigned a3,
                                         unsigned b0, unsigned b1) {
    asm volatile("mma.sync.aligned.m16n8k8.row.col.f32.tf32.tf32.f32 "
                 "{%0,%1,%2,%3}, {%4,%5,%6,%7}, {%8,%9}, {%0,%1,%2,%3};"
                 : "+f"(c0), "+f"(c1), "+f"(c2), "+f"(c3)
                 : "r"(a0), "r"(a1), "r"(a2), "r"(a3), "r"(b0), "r"(b1));
}

// ---------------------------------------------------------------------------
// Split x[B,L,C,2] into two contiguous streams
// ---------------------------------------------------------------------------
__global__ void split_kernel(const float2* __restrict__ x,
                             float* __restrict__ e, float* __restrict__ p) {
    int i = blockIdx.x * blockDim.x + threadIdx.x;
    if (i < MROWS * CDIM) {
        float2 v = x[i];
        e[i] = v.x;
        p[i] = v.y;
    }
}

// ---------------------------------------------------------------------------
// Projection GEMM (tf32 mma): Y[M,N] = X[M,256] @ W[256,N]
// Block: 256 threads (8 warps), tile 128 rows x TN cols. Warp = 16 rows x TN.
// ---------------------------------------------------------------------------
template<int TN>
__global__ __launch_bounds__(256)
void proj_mma(const float* __restrict__ X, const float* __restrict__ W,
              float* __restrict__ Y, int N, const float* __restrict__ gate) {
    if (gate && gate[0] == 0.0f) return;

    __shared__ float Xs[128][36];        // pitch 36 -> conflict-free A-frag reads
    __shared__ float Ws[32][TN + 8];     // pitch % 32 == 8 -> conflict-free B-frag reads

    const int tid = threadIdx.x, w = tid >> 5, lane = tid & 31;
    const int qr = lane >> 2, qc = lane & 3;
    const int m0 = blockIdx.y * 128, n0 = blockIdx.x * TN;
    constexpr int NT = TN / 8;

    float acc[NT][4];
#pragma unroll
    for (int nt = 0; nt < NT; nt++)
        acc[nt][0] = acc[nt][1] = acc[nt][2] = acc[nt][3] = 0.0f;

    for (int k0 = 0; k0 < CDIM; k0 += 32) {
#pragma unroll
        for (int t = 0; t < 16; t++) {
            int e = tid + t * 256; int r = e >> 5, c = e & 31;
            Xs[r][c] = cvt_tf32f(X[(size_t)(m0 + r) * CDIM + k0 + c]);
        }
#pragma unroll
        for (int t = 0; t < (32 * TN) / 256; t++) {
            int e = tid + t * 256; int r = e / TN, c = e % TN;
            Ws[r][c] = cvt_tf32f(W[(size_t)(k0 + r) * N + n0 + c]);
        }
        __syncthreads();

        const int r = w * 16 + qr;
#pragma unroll
        for (int kt = 0; kt < 4; kt++) {
            unsigned a0 = fasu(Xs[r][kt * 8 + qc]);
            unsigned a1 = fasu(Xs[r + 8][kt * 8 + qc]);
            unsigned a2 = fasu(Xs[r][kt * 8 + qc + 4]);
            unsigned a3 = fasu(Xs[r + 8][kt * 8 + qc + 4]);
#pragma unroll
            for (int nt = 0; nt < NT; nt++) {
                unsigned b0 = fasu(Ws[kt * 8 + qc][nt * 8 + qr]);
                unsigned b1 = fasu(Ws[kt * 8 + qc + 4][nt * 8 + qr]);
                mma_tf32(acc[nt][0], acc[nt][1], acc[nt][2], acc[nt][3],
                         a0, a1, a2, a3, b0, b1);
            }
        }
        __syncthreads();
    }

    const int r = m0 + w * 16 + qr;
#pragma unroll
    for (int nt = 0; nt < NT; nt++) {
        int c = n0 + nt * 8 + 2 * qc;
        *(float2*)&Y[(size_t)r * N + c]       = make_float2(acc[nt][0], acc[nt][1]);
        *(float2*)&Y[(size_t)(r + 8) * N + c] = make_float2(acc[nt][2], acc[nt][3]);
    }
}

// ---------------------------------------------------------------------------
// Flash attention with tf32 mma + register-resident online softmax.
// TQ=128 rows/block, TK=64 keys/tile. 8 warps; warp = 16 query rows, full N.
// blockIdx.z selects which of up to 2 attentions this block handles.
// ---------------------------------------------------------------------------
struct AttnPtrs { const float* Q[2]; const float* K[2]; const float* V[2]; };

struct AttnSmem2 {
    float Ks[TK][36];     // pitch 36: QK B-frag bank = 4*(t/4)+t%4 (bijective)
    float Vs[TK][264];    // pitch 264: PV B-frag bank = 8*(t%4)+t/4 (bijective)
    float Ps[TQ][68];     // pitch 68: PV A-frag bank = 4*(t/4)+t%4 (bijective)
};
extern __shared__ char attn_smem_raw[];

__global__ __launch_bounds__(256)
void attn_mma(AttnPtrs ap, float* __restrict__ out,
              const float* __restrict__ gate, int addMode, int chan0) {
    if (gate && gate[0] == 0.0f) return;
    const float gv = gate ? gate[0] : 1.0f;

    AttnSmem2& s = *reinterpret_cast<AttnSmem2*>(attn_smem_raw);
    const int tid = threadIdx.x, w = tid >> 5, lane = tid & 31;
    const int qr = lane >> 2, qc = lane & 3;
    const int qt = blockIdx.x, b = blockIdx.y, z = blockIdx.z;
    const int chanOff = chan0 + z * CDIM;

    const float* Qb = ap.Q[z] + ((size_t)b * LSEQ + (size_t)qt * TQ) * DDIM;
    const float* Kb = ap.K[z] + (size_t)b * LSEQ * DDIM;
    const float* Vb = ap.V[z] + (size_t)b * LSEQ * CDIM;

    const int r0 = w * 16 + qr;
    const float isc = rsqrtf((float)DDIM);

    // Q fragments live in registers for the whole kernel (A operand of QK^T)
    unsigned qa[4][4];
#pragma unroll
    for (int kt = 0; kt < 4; kt++) {
        qa[kt][0] = cvt_tf32(Qb[(size_t)r0 * DDIM + kt * 8 + qc] * isc);
        qa[kt][1] = cvt_tf32(Qb[(size_t)(r0 + 8) * DDIM + kt * 8 + qc] * isc);
        qa[kt][2] = cvt_tf32(Qb[(size_t)r0 * DDIM + kt * 8 + qc + 4] * isc);
        qa[kt][3] = cvt_tf32(Qb[(size_t)(r0 + 8) * DDIM + kt * 8 + qc + 4] * isc);
    }

    float acc[32][4];
#pragma unroll
    for (int nt = 0; nt < 32; nt++)
        acc[nt][0] = acc[nt][1] = acc[nt][2] = acc[nt][3] = 0.0f;
    float m0 = -3.402823466e38f, m1 = -3.402823466e38f, l0 = 0.0f, l1 = 0.0f;

    for (int j0 = 0; j0 < LSEQ; j0 += TK) {
        __syncthreads();   // prior iter's PV consumed Ks/Vs/Ps

        // K tile 64x32 (contiguous)
#pragma unroll
        for (int t = 0; t < 8; t++) {
            int e = tid + t * 256; int r = e >> 5, c = e & 31;
            s.Ks[r][c] = cvt_tf32f(Kb[(size_t)j0 * DDIM + e]);
        }
        // V tile 64x256 as float4 (contiguous)
        const float4* Vt = (const float4*)(Vb + (size_t)j0 * CDIM);
#pragma unroll
        for (int t = 0; t < 16; t++) {
            int e = tid + t * 256; int r = e >> 6, c4 = e & 63;
            float4 v = Vt[e];
            v.x = cvt_tf32f(v.x); v.y = cvt_tf32f(v.y);
            v.z = cvt_tf32f(v.z); v.w = cvt_tf32f(v.w);
            *(float4*)&s.Vs[r][c4 * 4] = v;
        }
        __syncthreads();

        // ---- S = Q K^T (16 rows x 64 keys per warp) ----
        float sf[8][4];
#pragma unroll
        for (int nt = 0; nt < 8; nt++)
            sf[nt][0] = sf[nt][1] = sf[nt][2] = sf[nt][3] = 0.0f;
#pragma unroll
        for (int kt = 0; kt < 4; kt++) {
#pragma unroll
            for (int nt = 0; nt < 8; nt++) {
                unsigned b0 = fasu(s.Ks[nt * 8 + qr][kt * 8 + qc]);
                unsigned b1 = fasu(s.Ks[nt * 8 + qr][kt * 8 + qc + 4]);
                mma_tf32(sf[nt][0], sf[nt][1], sf[nt][2], sf[nt][3],
                         qa[kt][0], qa[kt][1], qa[kt][2], qa[kt][3], b0, b1);
            }
        }

        // ---- online softmax (registers + quad shuffles only) ----
        float rm0 = -3.402823466e38f, rm1 = -3.402823466e38f;
#pragma unroll
        for (int nt = 0; nt < 8; nt++) {
            rm0 = fmaxf(rm0, fmaxf(sf[nt][0], sf[nt][1]));
            rm1 = fmaxf(rm1, fmaxf(sf[nt][2], sf[nt][3]));
        }
        rm0 = fmaxf(rm0, __shfl_xor_sync(0xffffffffu, rm0, 1));
        rm0 = fmaxf(rm0, __shfl_xor_sync(0xffffffffu, rm0, 2));
        rm1 = fmaxf(rm1, __shfl_xor_sync(0xffffffffu, rm1, 1));
        rm1 = fmaxf(rm1, __shfl_xor_sync(0xffffffffu, rm1, 2));
        float nm0 = fmaxf(m0, rm0), nm1 = fmaxf(m1, rm1);
        float sc0 = __expf(m0 - nm0), sc1 = __expf(m1 - nm1);
        float rs0 = 0.0f, rs1 = 0.0f;
#pragma unroll
        for (int nt = 0; nt < 8; nt++) {
            sf[nt][0] = __expf(sf[nt][0] - nm0); sf[nt][1] = __expf(sf[nt][1] - nm0);
            sf[nt][2] = __expf(sf[nt][2] - nm1); sf[nt][3] = __expf(sf[nt][3] - nm1);
            rs0 += sf[nt][0] + sf[nt][1];
            rs1 += sf[nt][2] + sf[nt][3];
        }
        rs0 += __shfl_xor_sync(0xffffffffu, rs0, 1);
        rs0 += __shfl_xor_sync(0xffffffffu, rs0, 2);
        rs1 += __shfl_xor_sync(0xffffffffu, rs1, 1);
        rs1 += __shfl_xor_sync(0xffffffffu, rs1, 2);
        l0 = l0 * sc0 + rs0; l1 = l1 * sc1 + rs1;
        m0 = nm0; m1 = nm1;
        if (sc0 != 1.0f || sc1 != 1.0f) {   // skip rescale when max unchanged
#pragma unroll
            for (int nt = 0; nt < 32; nt++) {
                acc[nt][0] *= sc0; acc[nt][1] *= sc0;
                acc[nt][2] *= sc1; acc[nt][3] *= sc1;
            }
        }

        // ---- P to smem (warp-private rows -> only syncwarp needed) ----
#pragma unroll
        for (int nt = 0; nt < 8; nt++) {
            *(float2*)&s.Ps[r0][nt * 8 + 2 * qc] =
                make_float2(cvt_tf32f(sf[nt][0]), cvt_tf32f(sf[nt][1]));
            *(float2*)&s.Ps[r0 + 8][nt * 8 + 2 * qc] =
                make_float2(cvt_tf32f(sf[nt][2]), cvt_tf32f(sf[nt][3]));
        }
        __syncwarp();

        // ---- acc += P V (16 rows x 256 cols per warp) ----
#pragma unroll
        for (int kt = 0; kt < 8; kt++) {
            unsigned a0 = fasu(s.Ps[r0][kt * 8 + qc]);
            unsigned a1 = fasu(s.Ps[r0 + 8][kt * 8 + qc]);
            unsigned a2 = fasu(s.Ps[r0][kt * 8 + qc + 4]);
            unsigned a3 = fasu(s.Ps[r0 + 8][kt * 8 + qc + 4]);
#pragma unroll
            for (int nt = 0; nt < 32; nt++) {
                unsigned b0 = fasu(s.Vs[kt * 8 + qc][nt * 8 + qr]);
                unsigned b1 = fasu(s.Vs[kt * 8 + qc + 4][nt * 8 + qr]);
                mma_tf32(acc[nt][0], acc[nt][1], acc[nt][2], acc[nt][3],
                         a0, a1, a2, a3, b0, b1);
            }
        }
    }

    // ---- epilogue ----
    float il0 = 1.0f / l0, il1 = 1.0f / l1;
    size_t gr = (size_t)b * LSEQ + (size_t)qt * TQ + r0;
    float* o0 = out + gr * (2 * CDIM) + chanOff;
    float* o1 = o0 + (size_t)8 * (2 * CDIM);
    if (addMode) {
#pragma unroll
        for (int nt = 0; nt < 32; nt++) {
            int c = nt * 8 + 2 * qc;
            o0[c]     += gv * acc[nt][0] * il0;
            o0[c + 1] += gv * acc[nt][1] * il0;
            o1[c]     += gv * acc[nt][2] * il1;
            o1[c + 1] += gv * acc[nt][3] * il1;
        }
    } else {
#pragma unroll
        for (int nt = 0; nt < 32; nt++) {
            int c = nt * 8 + 2 * qc;
            *(float2*)&o0[c] = make_float2(acc[nt][0] * il0, acc[nt][1] * il0);
            *(float2*)&o1[c] = make_float2(acc[nt][2] * il1, acc[nt][3] * il1);
        }
    }
}

// ---------------------------------------------------------------------------
// Launcher
// ---------------------------------------------------------------------------
extern "C" void kernel_launch(void* const* d_in, const int* in_sizes, int n_in,
                              void* d_out, int out_size) {
    const float* x = (const float*)d_in[0];
    const float* w[13];
    for (int i = 1; i <= 12; i++) w[i] = (const float*)d_in[i];
    const float* alpha = (const float*)d_in[13];
    const float* gamma = (const float*)d_in[14];
    float* out = (float*)d_out;

    float *ecg, *pcg, *Qb, *Kb, *Vb;
    cudaGetSymbolAddress((void**)&ecg, g_ecg);
    cudaGetSymbolAddress((void**)&pcg, g_pcg);
    cudaGetSymbolAddress((void**)&Qb,  g_Qs);
    cudaGetSymbolAddress((void**)&Kb,  g_Ks);
    cudaGetSymbolAddress((void**)&Vb,  g_Vs);

    auto Q = [&](int a) { return Qb + (size_t)a * MROWS * DDIM; };
    auto K = [&](int a) { return Kb + (size_t)a * MROWS * DDIM; };
    auto V = [&](int a) { return Vb + (size_t)a * MROWS * CDIM; };

    cudaFuncSetAttribute(attn_mma,
                         cudaFuncAttributeMaxDynamicSharedMemorySize,
                         (int)sizeof(AttnSmem2));

    // 1) de-interleave x
    split_kernel<<<(MROWS * CDIM + 255) / 256, 256>>>((const float2*)x, ecg, pcg);

    // 2) projections (tf32 mma)
    dim3 gQK(1, MROWS / 128);            // N = 32
    dim3 gV(CDIM / 64, MROWS / 128);     // N = 256, TN = 64
    // inter attn0: Q=ecg@w4, K=pcg@w5, V=pcg@w6
    proj_mma<32><<<gQK, 256>>>(ecg, w[4],  Q(0), DDIM, nullptr);
    proj_mma<32><<<gQK, 256>>>(pcg, w[5],  K(0), DDIM, nullptr);
    proj_mma<64><<<gV,  256>>>(pcg, w[6],  V(0), CDIM, nullptr);
    // inter attn1: Q=pcg@w10, K=ecg@w11, V=ecg@w12
    proj_mma<32><<<gQK, 256>>>(pcg, w[10], Q(1), DDIM, nullptr);
    proj_mma<32><<<gQK, 256>>>(ecg, w[11], K(1), DDIM, nullptr);
    proj_mma<64><<<gV,  256>>>(ecg, w[12], V(1), CDIM, nullptr);
    // intra attn2 (gated by alpha): w1, w2, w3
    proj_mma<32><<<gQK, 256>>>(ecg, w[1],  Q(2), DDIM, alpha);
    proj_mma<32><<<gQK, 256>>>(ecg, w[2],  K(2), DDIM, alpha);
    proj_mma<64><<<gV,  256>>>(ecg, w[3],  V(2), CDIM, alpha);
    // intra attn3 (gated by gamma): w7, w8, w9
    proj_mma<32><<<gQK, 256>>>(pcg, w[7],  Q(3), DDIM, gamma);
    proj_mma<32><<<gQK, 256>>>(pcg, w[8],  K(3), DDIM, gamma);
    proj_mma<64><<<gV,  256>>>(pcg, w[9],  V(3), CDIM, gamma);

    // 3) attentions: both ungated attns in ONE launch (z = 0,1)
    size_t smem = sizeof(AttnSmem2);
    AttnPtrs ap{};
    ap.Q[0] = Q(0); ap.K[0] = K(0); ap.V[0] = V(0);
    ap.Q[1] = Q(1); ap.K[1] = K(1); ap.V[1] = V(1);
    attn_mma<<<dim3(LSEQ / TQ, NBATCH, 2), 256, smem>>>(ap, out, nullptr, 0, 0);

    // gated intra attentions (skip instantly when gate == 0)
    AttnPtrs a2{}; a2.Q[0] = Q(2); a2.K[0] = K(2); a2.V[0] = V(2);
    attn_mma<<<dim3(LSEQ / TQ, NBATCH, 1), 256, smem>>>(a2, out, alpha, 1, 0);
    AttnPtrs a3{}; a3.Q[0] = Q(3); a3.K[0] = K(3); a3.V[0] = V(3);
    attn_mma<<<dim3(LSEQ / TQ, NBATCH, 1), 256, smem>>>(a3, out, gamma, 1, CDIM);
}

// round 7
// speedup vs baseline: 3.2361x; 1.9353x over previous
#include <cuda_runtime.h>
#include <cuda_fp16.h>
#include <math.h>

#define NBATCH 8
#define LSEQ   2048
#define CDIM   256
#define DDIM   32
#define MROWS  (NBATCH * LSEQ)   // 16384
#define NTILES (LSEQ / 64)       // 32 key tiles

// ---------------------------------------------------------------------------
// Device scratch
// ---------------------------------------------------------------------------
__device__ float  g_ecg[MROWS * CDIM];
__device__ float  g_pcg[MROWS * CDIM];
__device__ float  g_QK[4][MROWS * 64];       // fused [Q|K] fp32, row stride 64
__device__ __half g_Vh[4][MROWS * CDIM];     // V scratch fp16

// ---------------------------------------------------------------------------
// Helpers
// ---------------------------------------------------------------------------
__device__ __forceinline__ unsigned cvt_tf32(float f) {
    unsigned u; asm("cvt.rna.tf32.f32 %0, %1;" : "=r"(u) : "f"(f)); return u;
}
__device__ __forceinline__ float cvt_tf32f(float f) {
    return __uint_as_float(cvt_tf32(f));
}
__device__ __forceinline__ unsigned fasu(float f) { return __float_as_uint(f); }

__device__ __forceinline__ void mma_tf32(float* c,
                                         unsigned a0, unsigned a1, unsigned a2, unsigned a3,
                                         unsigned b0, unsigned b1) {
    asm volatile("mma.sync.aligned.m16n8k8.row.col.f32.tf32.tf32.f32 "
                 "{%0,%1,%2,%3}, {%4,%5,%6,%7}, {%8,%9}, {%0,%1,%2,%3};"
                 : "+f"(c[0]), "+f"(c[1]), "+f"(c[2]), "+f"(c[3])
                 : "r"(a0), "r"(a1), "r"(a2), "r"(a3), "r"(b0), "r"(b1));
}

__device__ __forceinline__ void mma16(float* c, const unsigned* a,
                                      unsigned b0, unsigned b1) {
    asm volatile("mma.sync.aligned.m16n8k16.row.col.f32.f16.f16.f32 "
                 "{%0,%1,%2,%3}, {%4,%5,%6,%7}, {%8,%9}, {%0,%1,%2,%3};"
                 : "+f"(c[0]), "+f"(c[1]), "+f"(c[2]), "+f"(c[3])
                 : "r"(a[0]), "r"(a[1]), "r"(a[2]), "r"(a[3]), "r"(b0), "r"(b1));
}

__device__ __forceinline__ unsigned h2u(__half2 h) { return *reinterpret_cast<unsigned*>(&h); }

// split x into fp16 hi + fp16 lo (packed pairs)
__device__ __forceinline__ void split2(float x, float y, unsigned& hi, unsigned& lo) {
    __half2 h = __floats2half2_rn(x, y);
    float2 hf = __half22float2(h);
    __half2 l = __floats2half2_rn(x - hf.x, y - hf.y);
    hi = h2u(h); lo = h2u(l);
}

__device__ __forceinline__ unsigned su(const void* p) {
    return (unsigned)__cvta_generic_to_shared(p);
}
#define CP16(dst, src) \
    asm volatile("cp.async.cg.shared.global [%0], [%1], 16;" :: "r"(dst), "l"(src))
#define CP_COMMIT() asm volatile("cp.async.commit_group;")

// ---------------------------------------------------------------------------
// Split x[B,L,C,2] into two streams
// ---------------------------------------------------------------------------
__global__ void split_kernel(const float2* __restrict__ x,
                             float* __restrict__ e, float* __restrict__ p) {
    int i = blockIdx.x * blockDim.x + threadIdx.x;
    if (i < MROWS * CDIM) {
        float2 v = x[i];
        e[i] = v.x;
        p[i] = v.y;
    }
}

// ---------------------------------------------------------------------------
// High-precision fused QK projection: Y[M][64] = X @ [Wa | Wb]
// split-tf32 (3-mma) => ~fp32 accuracy. 256 threads, 128-row tiles.
// ---------------------------------------------------------------------------
__global__ __launch_bounds__(256)
void proj_qk3(const float* __restrict__ X,
              const float* __restrict__ Wa, const float* __restrict__ Wb,
              float* __restrict__ Y, const float* __restrict__ gate) {
    if (gate && gate[0] == 0.0f) return;

    __shared__ float Xh[128][36], Xl[128][36];
    __shared__ float Wh[32][72], Wl[32][72];

    const int tid = threadIdx.x, w = tid >> 5, lane = tid & 31;
    const int qr = lane >> 2, qc = lane & 3;
    const int m0 = blockIdx.y * 128;

    float acc[8][4];
#pragma unroll
    for (int nt = 0; nt < 8; nt++)
        acc[nt][0] = acc[nt][1] = acc[nt][2] = acc[nt][3] = 0.0f;

    for (int k0 = 0; k0 < CDIM; k0 += 32) {
#pragma unroll
        for (int t = 0; t < 16; t++) {
            int e = tid + t * 256; int r = e >> 5, c = e & 31;
            float f = X[(size_t)(m0 + r) * CDIM + k0 + c];
            float h = cvt_tf32f(f);
            Xh[r][c] = h; Xl[r][c] = cvt_tf32f(f - h);
        }
#pragma unroll
        for (int t = 0; t < 8; t++) {
            int e = tid + t * 256; int r = e >> 6, c = e & 63;
            float f = (c < 32) ? Wa[(size_t)(k0 + r) * DDIM + c]
                               : Wb[(size_t)(k0 + r) * DDIM + (c - 32)];
            float h = cvt_tf32f(f);
            Wh[r][c] = h; Wl[r][c] = cvt_tf32f(f - h);
        }
        __syncthreads();

        const int r = w * 16 + qr;
#pragma unroll
        for (int kt = 0; kt < 4; kt++) {
            unsigned ah0 = fasu(Xh[r][kt * 8 + qc]);
            unsigned ah1 = fasu(Xh[r + 8][kt * 8 + qc]);
            unsigned ah2 = fasu(Xh[r][kt * 8 + qc + 4]);
            unsigned ah3 = fasu(Xh[r + 8][kt * 8 + qc + 4]);
            unsigned al0 = fasu(Xl[r][kt * 8 + qc]);
            unsigned al1 = fasu(Xl[r + 8][kt * 8 + qc]);
            unsigned al2 = fasu(Xl[r][kt * 8 + qc + 4]);
            unsigned al3 = fasu(Xl[r + 8][kt * 8 + qc + 4]);
#pragma unroll
            for (int nt = 0; nt < 8; nt++) {
                unsigned bh0 = fasu(Wh[kt * 8 + qc][nt * 8 + qr]);
                unsigned bh1 = fasu(Wh[kt * 8 + qc + 4][nt * 8 + qr]);
                unsigned bl0 = fasu(Wl[kt * 8 + qc][nt * 8 + qr]);
                unsigned bl1 = fasu(Wl[kt * 8 + qc + 4][nt * 8 + qr]);
                mma_tf32(acc[nt], ah0, ah1, ah2, ah3, bh0, bh1);
                mma_tf32(acc[nt], al0, al1, al2, al3, bh0, bh1);
                mma_tf32(acc[nt], ah0, ah1, ah2, ah3, bl0, bl1);
            }
        }
        __syncthreads();
    }

    const int r = m0 + w * 16 + qr;
#pragma unroll
    for (int nt = 0; nt < 8; nt++) {
        int c = nt * 8 + 2 * qc;
        *(float2*)&Y[(size_t)r * 64 + c]       = make_float2(acc[nt][0], acc[nt][1]);
        *(float2*)&Y[(size_t)(r + 8) * 64 + c] = make_float2(acc[nt][2], acc[nt][3]);
    }
}

// ---------------------------------------------------------------------------
// V projection (tf32 mma, fp16 output): Y[M][256] = X @ W
// ---------------------------------------------------------------------------
__global__ __launch_bounds__(256)
void proj_v(const float* __restrict__ X, const float* __restrict__ W,
            __half* __restrict__ Y, const float* __restrict__ gate) {
    if (gate && gate[0] == 0.0f) return;

    __shared__ float Xs[128][36];
    __shared__ float Ws[32][72];

    const int tid = threadIdx.x, w = tid >> 5, lane = tid & 31;
    const int qr = lane >> 2, qc = lane & 3;
    const int m0 = blockIdx.y * 128, n0 = blockIdx.x * 64;

    float acc[8][4];
#pragma unroll
    for (int nt = 0; nt < 8; nt++)
        acc[nt][0] = acc[nt][1] = acc[nt][2] = acc[nt][3] = 0.0f;

    for (int k0 = 0; k0 < CDIM; k0 += 32) {
#pragma unroll
        for (int t = 0; t < 16; t++) {
            int e = tid + t * 256; int r = e >> 5, c = e & 31;
            Xs[r][c] = cvt_tf32f(X[(size_t)(m0 + r) * CDIM + k0 + c]);
        }
#pragma unroll
        for (int t = 0; t < 8; t++) {
            int e = tid + t * 256; int r = e >> 6, c = e & 63;
            Ws[r][c] = cvt_tf32f(W[(size_t)(k0 + r) * CDIM + n0 + c]);
        }
        __syncthreads();

        const int r = w * 16 + qr;
#pragma unroll
        for (int kt = 0; kt < 4; kt++) {
            unsigned a0 = fasu(Xs[r][kt * 8 + qc]);
            unsigned a1 = fasu(Xs[r + 8][kt * 8 + qc]);
            unsigned a2 = fasu(Xs[r][kt * 8 + qc + 4]);
            unsigned a3 = fasu(Xs[r + 8][kt * 8 + qc + 4]);
#pragma unroll
            for (int nt = 0; nt < 8; nt++) {
                unsigned b0 = fasu(Ws[kt * 8 + qc][nt * 8 + qr]);
                unsigned b1 = fasu(Ws[kt * 8 + qc + 4][nt * 8 + qr]);
                mma_tf32(acc[nt], a0, a1, a2, a3, b0, b1);
            }
        }
        __syncthreads();
    }

    const int r = m0 + w * 16 + qr;
#pragma unroll
    for (int nt = 0; nt < 8; nt++) {
        int c = n0 + nt * 8 + 2 * qc;
        *(__half2*)&Y[(size_t)r * CDIM + c] = __floats2half2_rn(acc[nt][0], acc[nt][1]);
        *(__half2*)&Y[(size_t)(r + 8) * CDIM + c] = __floats2half2_rn(acc[nt][2], acc[nt][3]);
    }
}

// ---------------------------------------------------------------------------
// Flash attention, fp16 mma, P-in-registers, cp.async double buffer.
// Block: 256 threads = 8 warps as 4 row-groups x 2 col-groups.
// Block tile: 64 query rows x 256 out cols; key tiles of 64.
// QK^T uses split-fp16 (3 mmas) on fp32 Q/K for ~fp32 score accuracy.
// ---------------------------------------------------------------------------
struct AttnArgs { const float* Q[2]; const float* K[2]; const __half* V[2]; };

struct ASmem {
    float  Kraw[2][64][36];   // raw fp32 K tiles (cp.async)
    __half Khi[64][40];       // fp16 hi/lo split of current K tile
    __half Klo[64][40];
    __half Vs[2][64][264];    // fp16 V tiles (cp.async), ldmatrix-friendly
};
extern __shared__ char attn_raw[];

__global__ __launch_bounds__(256)
void attn16(AttnArgs args, float* __restrict__ out,
            const float* __restrict__ gate, int addMode, int chan0) {
    if (gate && gate[0] == 0.0f) return;
    const float gv = gate ? gate[0] : 1.0f;

    ASmem* S = reinterpret_cast<ASmem*>(attn_raw);
    const int tid = threadIdx.x, w = tid >> 5, lane = tid & 31;
    const int qr = lane >> 2, qc = lane & 3;
    const int wr = w >> 1, wc = w & 1;
    const int qt = blockIdx.x, b = blockIdx.y, z = blockIdx.z;
    const int r0 = wr * 16 + qr;          // block-local query row
    const int c0 = wc * 128;              // out-col base for this warp

    const size_t rowbase = (size_t)b * LSEQ + (size_t)qt * 64;
    const float* Qp = args.Q[z] + rowbase * 64;       // row stride 64
    const float* Kp = args.K[z] + (size_t)b * LSEQ * 64;
    const __half* Vp = args.V[z] + (size_t)b * LSEQ * CDIM;
    const float isc = rsqrtf((float)DDIM);

    // ---- Q fragments: fp32 -> hi/lo fp16 (A of m16n8k16), D=32 -> 2 chunks
    unsigned qh[2][4], ql[2][4];
#pragma unroll
    for (int kt = 0; kt < 2; kt++) {
        float2 fa = *(const float2*)&Qp[(size_t)r0 * 64 + kt * 16 + 2 * qc];
        float2 fb = *(const float2*)&Qp[(size_t)(r0 + 8) * 64 + kt * 16 + 2 * qc];
        float2 fc = *(const float2*)&Qp[(size_t)r0 * 64 + kt * 16 + 2 * qc + 8];
        float2 fd = *(const float2*)&Qp[(size_t)(r0 + 8) * 64 + kt * 16 + 2 * qc + 8];
        split2(fa.x * isc, fa.y * isc, qh[kt][0], ql[kt][0]);
        split2(fb.x * isc, fb.y * isc, qh[kt][1], ql[kt][1]);
        split2(fc.x * isc, fc.y * isc, qh[kt][2], ql[kt][2]);
        split2(fd.x * isc, fd.y * isc, qh[kt][3], ql[kt][3]);
    }

    float acc[16][4];
#pragma unroll
    for (int nt = 0; nt < 16; nt++)
        acc[nt][0] = acc[nt][1] = acc[nt][2] = acc[nt][3] = 0.0f;
    float m0v = -3.402823466e38f, m1v = -3.402823466e38f, l0 = 0.0f, l1 = 0.0f;

    // ---- cp.async tile loader
    auto issue = [&](int t) {
        int bufi = t & 1;
        int j0 = t * 64;
        const __half* Vg = Vp + (size_t)j0 * CDIM;
#pragma unroll
        for (int i = 0; i < 8; i++) {
            int e = tid + i * 256; int key = e >> 5, c = e & 31;
            CP16(su(&S->Vs[bufi][key][c * 8]), Vg + (size_t)key * CDIM + c * 8);
        }
#pragma unroll
        for (int i = 0; i < 2; i++) {
            int e = tid + i * 256; int key = e >> 3, c = e & 7;
            CP16(su(&S->Kraw[bufi][key][c * 4]), Kp + (size_t)(j0 + key) * 64 + c * 4);
        }
        CP_COMMIT();
    };

    issue(0);
    issue(1);

    for (int t = 0; t < NTILES; t++) {
        const int bufi = t & 1;
        if (t + 1 < NTILES) asm volatile("cp.async.wait_group 1;");
        else                asm volatile("cp.async.wait_group 0;");
        __syncthreads();

        // ---- convert K tile to hi/lo fp16 (8 floats per thread)
        {
            int key = tid >> 2, d0 = (tid & 3) * 8;
#pragma unroll
            for (int j = 0; j < 4; j++) {
                float2 v = *(float2*)&S->Kraw[bufi][key][d0 + 2 * j];
                unsigned hi, lo; split2(v.x, v.y, hi, lo);
                *(unsigned*)&S->Khi[key][d0 + 2 * j] = hi;
                *(unsigned*)&S->Klo[key][d0 + 2 * j] = lo;
            }
        }
        __syncthreads();

        // ---- S = Q K^T, split-fp16 3-mma (16 rows x 64 keys per warp)
        float sf[8][4];
#pragma unroll
        for (int nt = 0; nt < 8; nt++)
            sf[nt][0] = sf[nt][1] = sf[nt][2] = sf[nt][3] = 0.0f;
#pragma unroll
        for (int kt = 0; kt < 2; kt++) {
#pragma unroll
            for (int nt = 0; nt < 8; nt++) {
                int key = nt * 8 + qr;
                unsigned bh0 = *(unsigned*)&S->Khi[key][kt * 16 + 2 * qc];
                unsigned bh1 = *(unsigned*)&S->Khi[key][kt * 16 + 2 * qc + 8];
                unsigned bl0 = *(unsigned*)&S->Klo[key][kt * 16 + 2 * qc];
                unsigned bl1 = *(unsigned*)&S->Klo[key][kt * 16 + 2 * qc + 8];
                mma16(sf[nt], qh[kt], bh0, bh1);
                mma16(sf[nt], ql[kt], bh0, bh1);
                mma16(sf[nt], qh[kt], bl0, bl1);
            }
        }

        // ---- online softmax (registers + quad shuffles)
        float rm0 = -3.402823466e38f, rm1 = -3.402823466e38f;
#pragma unroll
        for (int nt = 0; nt < 8; nt++) {
            rm0 = fmaxf(rm0, fmaxf(sf[nt][0], sf[nt][1]));
            rm1 = fmaxf(rm1, fmaxf(sf[nt][2], sf[nt][3]));
        }
        rm0 = fmaxf(rm0, __shfl_xor_sync(0xffffffffu, rm0, 1));
        rm0 = fmaxf(rm0, __shfl_xor_sync(0xffffffffu, rm0, 2));
        rm1 = fmaxf(rm1, __shfl_xor_sync(0xffffffffu, rm1, 1));
        rm1 = fmaxf(rm1, __shfl_xor_sync(0xffffffffu, rm1, 2));
        float nm0 = fmaxf(m0v, rm0), nm1 = fmaxf(m1v, rm1);
        float sc0 = __expf(m0v - nm0), sc1 = __expf(m1v - nm1);
        float rs0 = 0.0f, rs1 = 0.0f;
#pragma unroll
        for (int nt = 0; nt < 8; nt++) {
            sf[nt][0] = __expf(sf[nt][0] - nm0); sf[nt][1] = __expf(sf[nt][1] - nm0);
            sf[nt][2] = __expf(sf[nt][2] - nm1); sf[nt][3] = __expf(sf[nt][3] - nm1);
            rs0 += sf[nt][0] + sf[nt][1];
            rs1 += sf[nt][2] + sf[nt][3];
        }
        rs0 += __shfl_xor_sync(0xffffffffu, rs0, 1);
        rs0 += __shfl_xor_sync(0xffffffffu, rs0, 2);
        rs1 += __shfl_xor_sync(0xffffffffu, rs1, 1);
        rs1 += __shfl_xor_sync(0xffffffffu, rs1, 2);
        l0 = l0 * sc0 + rs0; l1 = l1 * sc1 + rs1;
        m0v = nm0; m1v = nm1;
        if (sc0 != 1.0f || sc1 != 1.0f) {
#pragma unroll
            for (int nt = 0; nt < 16; nt++) {
                acc[nt][0] *= sc0; acc[nt][1] *= sc0;
                acc[nt][2] *= sc1; acc[nt][3] *= sc1;
            }
        }

        // ---- pack P into A-fragments (S-frag layout == A-frag layout)
        unsigned pa[4][4];
#pragma unroll
        for (int kt = 0; kt < 4; kt++) {
            pa[kt][0] = h2u(__floats2half2_rn(sf[2 * kt][0],     sf[2 * kt][1]));
            pa[kt][1] = h2u(__floats2half2_rn(sf[2 * kt][2],     sf[2 * kt][3]));
            pa[kt][2] = h2u(__floats2half2_rn(sf[2 * kt + 1][0], sf[2 * kt + 1][1]));
            pa[kt][3] = h2u(__floats2half2_rn(sf[2 * kt + 1][2], sf[2 * kt + 1][3]));
        }

        // ---- acc += P V  (ldmatrix.x4.trans for V B-fragments)
#pragma unroll
        for (int kt = 0; kt < 4; kt++) {
#pragma unroll
            for (int np = 0; np < 8; np++) {
                unsigned b0, b1, b2, b3;
                unsigned addr = su(&S->Vs[bufi][kt * 16 + (lane & 15)]
                                         [c0 + np * 16 + (lane >> 4) * 8]);
                asm volatile("ldmatrix.sync.aligned.m8n8.x4.trans.shared.b16 "
                             "{%0,%1,%2,%3}, [%4];"
                             : "=r"(b0), "=r"(b1), "=r"(b2), "=r"(b3) : "r"(addr));
                mma16(acc[2 * np],     pa[kt], b0, b1);
                mma16(acc[2 * np + 1], pa[kt], b2, b3);
            }
        }

        __syncthreads();                       // everyone done with Vs[bufi]
        if (t + 2 < NTILES) issue(t + 2);      // safe: writes buf (t+2)&1 == bufi
    }

    // ---- epilogue
    float il0 = 1.0f / l0, il1 = 1.0f / l1;
    float* o0 = out + (rowbase + r0) * (2 * CDIM) + chan0 + z * CDIM + c0;
    float* o1 = o0 + (size_t)8 * (2 * CDIM);
    if (addMode) {
#pragma unroll
        for (int nt = 0; nt < 16; nt++) {
            int c = nt * 8 + 2 * qc;
            o0[c]     += gv * acc[nt][0] * il0;
            o0[c + 1] += gv * acc[nt][1] * il0;
            o1[c]     += gv * acc[nt][2] * il1;
            o1[c + 1] += gv * acc[nt][3] * il1;
        }
    } else {
#pragma unroll
        for (int nt = 0; nt < 16; nt++) {
            int c = nt * 8 + 2 * qc;
            *(float2*)&o0[c] = make_float2(acc[nt][0] * il0, acc[nt][1] * il0);
            *(float2*)&o1[c] = make_float2(acc[nt][2] * il1, acc[nt][3] * il1);
        }
    }
}

// ---------------------------------------------------------------------------
// Launcher
// ---------------------------------------------------------------------------
extern "C" void kernel_launch(void* const* d_in, const int* in_sizes, int n_in,
                              void* d_out, int out_size) {
    const float* x = (const float*)d_in[0];
    const float* w[13];
    for (int i = 1; i <= 12; i++) w[i] = (const float*)d_in[i];
    const float* alpha = (const float*)d_in[13];
    const float* gamma = (const float*)d_in[14];
    float* out = (float*)d_out;

    float *ecg, *pcg, *qk; __half* vh;
    cudaGetSymbolAddress((void**)&ecg, g_ecg);
    cudaGetSymbolAddress((void**)&pcg, g_pcg);
    cudaGetSymbolAddress((void**)&qk,  g_QK);
    cudaGetSymbolAddress((void**)&vh,  g_Vh);

    auto QK = [&](int a) { return qk + (size_t)a * MROWS * 64; };
    auto VH = [&](int a) { return vh + (size_t)a * MROWS * CDIM; };

    cudaFuncSetAttribute(attn16, cudaFuncAttributeMaxDynamicSharedMemorySize,
                         (int)sizeof(ASmem));

    // 1) de-interleave
    split_kernel<<<(MROWS * CDIM + 255) / 256, 256>>>((const float2*)x, ecg, pcg);

    // 2) projections
    dim3 gQ(1, MROWS / 128);
    dim3 gV(CDIM / 64, MROWS / 128);
    // fused [Q|K]:  QK0 = ecg@[w4|w11] = [Q0|K1]; QK1 = pcg@[w5|w10] = [K0|Q1]
    proj_qk3<<<gQ, 256>>>(ecg, w[4], w[11], QK(0), nullptr);
    proj_qk3<<<gQ, 256>>>(pcg, w[5], w[10], QK(1), nullptr);
    proj_qk3<<<gQ, 256>>>(ecg, w[1], w[2],  QK(2), alpha);   // [Q2|K2]
    proj_qk3<<<gQ, 256>>>(pcg, w[7], w[8],  QK(3), gamma);   // [Q3|K3]
    // V projections (fp16 out)
    proj_v<<<gV, 256>>>(pcg, w[6],  VH(0), nullptr);
    proj_v<<<gV, 256>>>(ecg, w[12], VH(1), nullptr);
    proj_v<<<gV, 256>>>(ecg, w[3],  VH(2), alpha);
    proj_v<<<gV, 256>>>(pcg, w[9],  VH(3), gamma);

    // 3) attention: both ungated paths in one launch (z = 0,1)
    size_t smem = sizeof(ASmem);
    AttnArgs ap{};
    ap.Q[0] = QK(0);      ap.K[0] = QK(1);      ap.V[0] = VH(0);   // z=0
    ap.Q[1] = QK(1) + 32; ap.K[1] = QK(0) + 32; ap.V[1] = VH(1);   // z=1
    attn16<<<dim3(LSEQ / 64, NBATCH, 2), 256, smem>>>(ap, out, nullptr, 0, 0);

    // gated intra paths
    AttnArgs a2{}; a2.Q[0] = QK(2); a2.K[0] = QK(2) + 32; a2.V[0] = VH(2);
    attn16<<<dim3(LSEQ / 64, NBATCH, 1), 256, smem>>>(a2, out, alpha, 1, 0);
    AttnArgs a3{}; a3.Q[0] = QK(3); a3.K[0] = QK(3) + 32; a3.V[0] = VH(3);
    attn16<<<dim3(LSEQ / 64, NBATCH, 1), 256, smem>>>(a3, out, gamma, 1, CDIM);
}

// round 8
// speedup vs baseline: 3.6174x; 1.1178x over previous
#include <cuda_runtime.h>
#include <cuda_fp16.h>
#include <math.h>

#define NBATCH 8
#define LSEQ   2048
#define CDIM   256
#define DDIM   32
#define MROWS  (NBATCH * LSEQ)   // 16384
#define NTILES (LSEQ / 64)       // 32 key tiles

// ---------------------------------------------------------------------------
// Device scratch
// ---------------------------------------------------------------------------
__device__ float  g_ecg[MROWS * CDIM];
__device__ float  g_pcg[MROWS * CDIM];
__device__ float  g_QK[4][MROWS * 64];       // fused [Q|K] fp32 (Q half valid)
__device__ __half g_Khi[4][MROWS * 32];      // K hi fp16, row stride 32
__device__ __half g_Klo[4][MROWS * 32];      // K lo fp16
__device__ __half g_Vh[4][MROWS * CDIM];     // V scratch fp16

// ---------------------------------------------------------------------------
// Helpers
// ---------------------------------------------------------------------------
__device__ __forceinline__ unsigned cvt_tf32(float f) {
    unsigned u; asm("cvt.rna.tf32.f32 %0, %1;" : "=r"(u) : "f"(f)); return u;
}
__device__ __forceinline__ float cvt_tf32f(float f) {
    return __uint_as_float(cvt_tf32(f));
}
__device__ __forceinline__ unsigned fasu(float f) { return __float_as_uint(f); }

__device__ __forceinline__ void mma_tf32(float* c,
                                         unsigned a0, unsigned a1, unsigned a2, unsigned a3,
                                         unsigned b0, unsigned b1) {
    asm volatile("mma.sync.aligned.m16n8k8.row.col.f32.tf32.tf32.f32 "
                 "{%0,%1,%2,%3}, {%4,%5,%6,%7}, {%8,%9}, {%0,%1,%2,%3};"
                 : "+f"(c[0]), "+f"(c[1]), "+f"(c[2]), "+f"(c[3])
                 : "r"(a0), "r"(a1), "r"(a2), "r"(a3), "r"(b0), "r"(b1));
}

__device__ __forceinline__ void mma16(float* c, const unsigned* a,
                                      unsigned b0, unsigned b1) {
    asm volatile("mma.sync.aligned.m16n8k16.row.col.f32.f16.f16.f32 "
                 "{%0,%1,%2,%3}, {%4,%5,%6,%7}, {%8,%9}, {%0,%1,%2,%3};"
                 : "+f"(c[0]), "+f"(c[1]), "+f"(c[2]), "+f"(c[3])
                 : "r"(a[0]), "r"(a[1]), "r"(a[2]), "r"(a[3]), "r"(b0), "r"(b1));
}

__device__ __forceinline__ unsigned h2u(__half2 h) { return *reinterpret_cast<unsigned*>(&h); }

__device__ __forceinline__ void split2(float x, float y, unsigned& hi, unsigned& lo) {
    __half2 h = __floats2half2_rn(x, y);
    float2 hf = __half22float2(h);
    __half2 l = __floats2half2_rn(x - hf.x, y - hf.y);
    hi = h2u(h); lo = h2u(l);
}

__device__ __forceinline__ unsigned su(const void* p) {
    return (unsigned)__cvta_generic_to_shared(p);
}
#define CP16(dst, src) \
    asm volatile("cp.async.cg.shared.global [%0], [%1], 16;" :: "r"(dst), "l"(src))
#define CP_COMMIT() asm volatile("cp.async.commit_group;")

#define LDSM_X4(r0, r1, r2, r3, addr) \
    asm volatile("ldmatrix.sync.aligned.m8n8.x4.shared.b16 {%0,%1,%2,%3}, [%4];" \
                 : "=r"(r0), "=r"(r1), "=r"(r2), "=r"(r3) : "r"(addr))
#define LDSM_X4T(r0, r1, r2, r3, addr) \
    asm volatile("ldmatrix.sync.aligned.m8n8.x4.trans.shared.b16 {%0,%1,%2,%3}, [%4];" \
                 : "=r"(r0), "=r"(r1), "=r"(r2), "=r"(r3) : "r"(addr))

// ---------------------------------------------------------------------------
// Split x[B,L,C,2] into two streams
// ---------------------------------------------------------------------------
__global__ void split_kernel(const float2* __restrict__ x,
                             float* __restrict__ e, float* __restrict__ p) {
    int i = blockIdx.x * blockDim.x + threadIdx.x;
    if (i < MROWS * CDIM) {
        float2 v = x[i];
        e[i] = v.x;
        p[i] = v.y;
    }
}

// ---------------------------------------------------------------------------
// Fused QK projection, split-tf32 (3-mma) for ~fp32 accuracy.
// Y[M][64] = X @ [Wa | Wb].  Q half written fp32 into Y; K half (selected by
// khalf) written as fp16 hi/lo into Khi/Klo (row stride 32).
// ---------------------------------------------------------------------------
__global__ __launch_bounds__(256)
void proj_qk3(const float* __restrict__ X,
              const float* __restrict__ Wa, const float* __restrict__ Wb,
              float* __restrict__ Y,
              __half* __restrict__ Khi, __half* __restrict__ Klo, int khalf,
              const float* __restrict__ gate) {
    if (gate && gate[0] == 0.0f) return;

    __shared__ float Xh[128][36], Xl[128][36];
    __shared__ float Wh[32][72], Wl[32][72];

    const int tid = threadIdx.x, w = tid >> 5, lane = tid & 31;
    const int qr = lane >> 2, qc = lane & 3;
    const int m0 = blockIdx.y * 128;

    float acc[8][4];
#pragma unroll
    for (int nt = 0; nt < 8; nt++)
        acc[nt][0] = acc[nt][1] = acc[nt][2] = acc[nt][3] = 0.0f;

    for (int k0 = 0; k0 < CDIM; k0 += 32) {
#pragma unroll
        for (int t = 0; t < 16; t++) {
            int e = tid + t * 256; int r = e >> 5, c = e & 31;
            float f = X[(size_t)(m0 + r) * CDIM + k0 + c];
            float h = cvt_tf32f(f);
            Xh[r][c] = h; Xl[r][c] = cvt_tf32f(f - h);
        }
#pragma unroll
        for (int t = 0; t < 8; t++) {
            int e = tid + t * 256; int r = e >> 6, c = e & 63;
            float f = (c < 32) ? Wa[(size_t)(k0 + r) * DDIM + c]
                               : Wb[(size_t)(k0 + r) * DDIM + (c - 32)];
            float h = cvt_tf32f(f);
            Wh[r][c] = h; Wl[r][c] = cvt_tf32f(f - h);
        }
        __syncthreads();

        const int r = w * 16 + qr;
#pragma unroll
        for (int kt = 0; kt < 4; kt++) {
            unsigned ah0 = fasu(Xh[r][kt * 8 + qc]);
            unsigned ah1 = fasu(Xh[r + 8][kt * 8 + qc]);
            unsigned ah2 = fasu(Xh[r][kt * 8 + qc + 4]);
            unsigned ah3 = fasu(Xh[r + 8][kt * 8 + qc + 4]);
            unsigned al0 = fasu(Xl[r][kt * 8 + qc]);
            unsigned al1 = fasu(Xl[r + 8][kt * 8 + qc]);
            unsigned al2 = fasu(Xl[r][kt * 8 + qc + 4]);
            unsigned al3 = fasu(Xl[r + 8][kt * 8 + qc + 4]);
#pragma unroll
            for (int nt = 0; nt < 8; nt++) {
                unsigned bh0 = fasu(Wh[kt * 8 + qc][nt * 8 + qr]);
                unsigned bh1 = fasu(Wh[kt * 8 + qc + 4][nt * 8 + qr]);
                unsigned bl0 = fasu(Wl[kt * 8 + qc][nt * 8 + qr]);
                unsigned bl1 = fasu(Wl[kt * 8 + qc + 4][nt * 8 + qr]);
                mma_tf32(acc[nt], ah0, ah1, ah2, ah3, bh0, bh1);
                mma_tf32(acc[nt], al0, al1, al2, al3, bh0, bh1);
                mma_tf32(acc[nt], ah0, ah1, ah2, ah3, bl0, bl1);
            }
        }
        __syncthreads();
    }

    const int r = m0 + w * 16 + qr;
#pragma unroll
    for (int nt = 0; nt < 8; nt++) {
        if ((nt >> 2) != khalf) {
            // Q half -> fp32
            int c = nt * 8 + 2 * qc;
            *(float2*)&Y[(size_t)r * 64 + c]       = make_float2(acc[nt][0], acc[nt][1]);
            *(float2*)&Y[(size_t)(r + 8) * 64 + c] = make_float2(acc[nt][2], acc[nt][3]);
        } else {
            // K half -> fp16 hi/lo, row stride 32
            int c = (nt - 4 * khalf) * 8 + 2 * qc;
            unsigned hi0, lo0, hi1, lo1;
            split2(acc[nt][0], acc[nt][1], hi0, lo0);
            split2(acc[nt][2], acc[nt][3], hi1, lo1);
            *(unsigned*)&Khi[(size_t)r * 32 + c]       = hi0;
            *(unsigned*)&Klo[(size_t)r * 32 + c]       = lo0;
            *(unsigned*)&Khi[(size_t)(r + 8) * 32 + c] = hi1;
            *(unsigned*)&Klo[(size_t)(r + 8) * 32 + c] = lo1;
        }
    }
}

// ---------------------------------------------------------------------------
// V projection, fp16 m16n8k16 + ldmatrix: Y[M][256] = X @ W, fp16 out.
// ---------------------------------------------------------------------------
__global__ __launch_bounds__(256)
void proj_v(const float* __restrict__ X, const float* __restrict__ W,
            __half* __restrict__ Y, const float* __restrict__ gate) {
    if (gate && gate[0] == 0.0f) return;

    __shared__ __half Xs[128][40];    // pitch 80B -> conflict-free ldmatrix
    __shared__ __half Ws[32][72];     // pitch 144B -> conflict-free ldmatrix

    const int tid = threadIdx.x, w = tid >> 5, lane = tid & 31;
    const int qr = lane >> 2, qc = lane & 3;
    const int m0 = blockIdx.y * 128, n0 = blockIdx.x * 64;

    float acc[8][4];
#pragma unroll
    for (int nt = 0; nt < 8; nt++)
        acc[nt][0] = acc[nt][1] = acc[nt][2] = acc[nt][3] = 0.0f;

    for (int k0 = 0; k0 < CDIM; k0 += 32) {
        // X tile 128x32 fp32 -> fp16 (half2 stores)
#pragma unroll
        for (int t = 0; t < 8; t++) {
            int e = tid + t * 256; int r = e >> 4, c2 = e & 15;
            float2 f = *(const float2*)&X[(size_t)(m0 + r) * CDIM + k0 + c2 * 2];
            *(__half2*)&Xs[r][c2 * 2] = __floats2half2_rn(f.x, f.y);
        }
        // W tile 32x64 fp32 -> fp16
#pragma unroll
        for (int t = 0; t < 4; t++) {
            int e = tid + t * 256; int r = e >> 5, c2 = e & 31;
            float2 f = *(const float2*)&W[(size_t)(k0 + r) * CDIM + n0 + c2 * 2];
            *(__half2*)&Ws[r][c2 * 2] = __floats2half2_rn(f.x, f.y);
        }
        __syncthreads();

        const int r0 = w * 16;
#pragma unroll
        for (int kt = 0; kt < 2; kt++) {
            unsigned a[4];
            unsigned aad = su(&Xs[r0 + (lane & 7) + ((lane >> 3) & 1) * 8]
                                 [kt * 16 + (lane >> 4) * 8]);
            LDSM_X4(a[0], a[1], a[2], a[3], aad);
#pragma unroll
            for (int np = 0; np < 4; np++) {
                unsigned b0, b1, b2, b3;
                unsigned bad = su(&Ws[kt * 16 + (lane & 15)]
                                     [np * 16 + (lane >> 4) * 8]);
                LDSM_X4T(b0, b1, b2, b3, bad);
                mma16(acc[2 * np],     a, b0, b1);
                mma16(acc[2 * np + 1], a, b2, b3);
            }
        }
        __syncthreads();
    }

    const int r = m0 + w * 16 + qr;
#pragma unroll
    for (int nt = 0; nt < 8; nt++) {
        int c = n0 + nt * 8 + 2 * qc;
        *(__half2*)&Y[(size_t)r * CDIM + c]       = __floats2half2_rn(acc[nt][0], acc[nt][1]);
        *(__half2*)&Y[(size_t)(r + 8) * CDIM + c] = __floats2half2_rn(acc[nt][2], acc[nt][3]);
    }
}

// ---------------------------------------------------------------------------
// Flash attention, fp16 mma, P-in-registers, cp.async double buffer.
// K comes in pre-split fp16 hi/lo; all frags via ldmatrix. 2 blocks/SM.
// ---------------------------------------------------------------------------
struct AttnArgs {
    const float*  Q[2];
    const __half* Khi[2];
    const __half* Klo[2];
    const __half* V[2];
};

struct ASmem {
    __half Khi[2][64][40];    // 80B pitch, conflict-free ldmatrix
    __half Klo[2][64][40];
    __half Vs[2][64][264];    // 528B pitch, conflict-free ldmatrix.trans
};
extern __shared__ char attn_raw[];

__global__ __launch_bounds__(256, 2)
void attn16(AttnArgs args, float* __restrict__ out,
            const float* __restrict__ gate, int addMode, int chan0) {
    if (gate && gate[0] == 0.0f) return;
    const float gv = gate ? gate[0] : 1.0f;

    ASmem* S = reinterpret_cast<ASmem*>(attn_raw);
    const int tid = threadIdx.x, w = tid >> 5, lane = tid & 31;
    const int qr = lane >> 2, qc = lane & 3;
    const int wr = w >> 1, wc = w & 1;
    const int qt = blockIdx.x, b = blockIdx.y, z = blockIdx.z;
    const int r0 = wr * 16 + qr;
    const int c0 = wc * 128;

    const size_t rowbase = (size_t)b * LSEQ + (size_t)qt * 64;
    const float*  Qp  = args.Q[z]   + rowbase * 64;
    const __half* Khp = args.Khi[z] + (size_t)b * LSEQ * 32;
    const __half* Klp = args.Klo[z] + (size_t)b * LSEQ * 32;
    const __half* Vp  = args.V[z]   + (size_t)b * LSEQ * CDIM;
    const float isc = rsqrtf((float)DDIM);

    // Q fragments fp32 -> hi/lo fp16
    unsigned qh[2][4], ql[2][4];
#pragma unroll
    for (int kt = 0; kt < 2; kt++) {
        float2 fa = *(const float2*)&Qp[(size_t)r0 * 64 + kt * 16 + 2 * qc];
        float2 fb = *(const float2*)&Qp[(size_t)(r0 + 8) * 64 + kt * 16 + 2 * qc];
        float2 fc = *(const float2*)&Qp[(size_t)r0 * 64 + kt * 16 + 2 * qc + 8];
        float2 fd = *(const float2*)&Qp[(size_t)(r0 + 8) * 64 + kt * 16 + 2 * qc + 8];
        split2(fa.x * isc, fa.y * isc, qh[kt][0], ql[kt][0]);
        split2(fb.x * isc, fb.y * isc, qh[kt][1], ql[kt][1]);
        split2(fc.x * isc, fc.y * isc, qh[kt][2], ql[kt][2]);
        split2(fd.x * isc, fd.y * isc, qh[kt][3], ql[kt][3]);
    }

    float acc[16][4];
#pragma unroll
    for (int nt = 0; nt < 16; nt++)
        acc[nt][0] = acc[nt][1] = acc[nt][2] = acc[nt][3] = 0.0f;
    float m0v = -3.402823466e38f, m1v = -3.402823466e38f, l0 = 0.0f, l1 = 0.0f;

    auto issue = [&](int t) {
        int bufi = t & 1;
        int j0 = t * 64;
        const __half* Vg = Vp + (size_t)j0 * CDIM;
#pragma unroll
        for (int i = 0; i < 8; i++) {
            int e = tid + i * 256; int key = e >> 5, c = e & 31;
            CP16(su(&S->Vs[bufi][key][c * 8]), Vg + (size_t)key * CDIM + c * 8);
        }
        // K hi/lo: 64 keys x 4 chunks each
#pragma unroll
        for (int i = 0; i < 2; i++) {
            int e = tid + i * 256; int key = e >> 3, c = e & 7;
            if (c < 4)
                CP16(su(&S->Khi[bufi][key][c * 8]),
                     Khp + (size_t)(j0 + key) * 32 + c * 8);
            else
                CP16(su(&S->Klo[bufi][key][(c - 4) * 8]),
                     Klp + (size_t)(j0 + key) * 32 + (c - 4) * 8);
        }
        CP_COMMIT();
    };

    issue(0);
    issue(1);

    for (int t = 0; t < NTILES; t++) {
        const int bufi = t & 1;
        if (t + 1 < NTILES) asm volatile("cp.async.wait_group 1;");
        else                asm volatile("cp.async.wait_group 0;");
        __syncthreads();

        // ---- S = Q K^T, split-fp16 3-mma; K frags via ldmatrix.x4
        float sf[8][4];
#pragma unroll
        for (int nt = 0; nt < 8; nt++)
            sf[nt][0] = sf[nt][1] = sf[nt][2] = sf[nt][3] = 0.0f;
#pragma unroll
        for (int kt = 0; kt < 2; kt++) {
#pragma unroll
            for (int ng = 0; ng < 4; ng++) {
                int krow = ng * 16 + (lane & 7) + ((lane >> 4) << 3);
                int dcol = kt * 16 + ((lane >> 3) & 1) * 8;
                unsigned bh0, bh1, bh2, bh3, bl0, bl1, bl2, bl3;
                LDSM_X4(bh0, bh1, bh2, bh3, su(&S->Khi[bufi][krow][dcol]));
                LDSM_X4(bl0, bl1, bl2, bl3, su(&S->Klo[bufi][krow][dcol]));
                mma16(sf[2 * ng],     qh[kt], bh0, bh1);
                mma16(sf[2 * ng],     ql[kt], bh0, bh1);
                mma16(sf[2 * ng],     qh[kt], bl0, bl1);
                mma16(sf[2 * ng + 1], qh[kt], bh2, bh3);
                mma16(sf[2 * ng + 1], ql[kt], bh2, bh3);
                mma16(sf[2 * ng + 1], qh[kt], bl2, bl3);
            }
        }

        // ---- online softmax (registers + quad shuffles)
        float rm0 = -3.402823466e38f, rm1 = -3.402823466e38f;
#pragma unroll
        for (int nt = 0; nt < 8; nt++) {
            rm0 = fmaxf(rm0, fmaxf(sf[nt][0], sf[nt][1]));
            rm1 = fmaxf(rm1, fmaxf(sf[nt][2], sf[nt][3]));
        }
        rm0 = fmaxf(rm0, __shfl_xor_sync(0xffffffffu, rm0, 1));
        rm0 = fmaxf(rm0, __shfl_xor_sync(0xffffffffu, rm0, 2));
        rm1 = fmaxf(rm1, __shfl_xor_sync(0xffffffffu, rm1, 1));
        rm1 = fmaxf(rm1, __shfl_xor_sync(0xffffffffu, rm1, 2));
        float nm0 = fmaxf(m0v, rm0), nm1 = fmaxf(m1v, rm1);
        float sc0 = __expf(m0v - nm0), sc1 = __expf(m1v - nm1);
        float rs0 = 0.0f, rs1 = 0.0f;
#pragma unroll
        for (int nt = 0; nt < 8; nt++) {
            sf[nt][0] = __expf(sf[nt][0] - nm0); sf[nt][1] = __expf(sf[nt][1] - nm0);
            sf[nt][2] = __expf(sf[nt][2] - nm1); sf[nt][3] = __expf(sf[nt][3] - nm1);
            rs0 += sf[nt][0] + sf[nt][1];
            rs1 += sf[nt][2] + sf[nt][3];
        }
        rs0 += __shfl_xor_sync(0xffffffffu, rs0, 1);
        rs0 += __shfl_xor_sync(0xffffffffu, rs0, 2);
        rs1 += __shfl_xor_sync(0xffffffffu, rs1, 1);
        rs1 += __shfl_xor_sync(0xffffffffu, rs1, 2);
        l0 = l0 * sc0 + rs0; l1 = l1 * sc1 + rs1;
        m0v = nm0; m1v = nm1;
        if (sc0 != 1.0f || sc1 != 1.0f) {
#pragma unroll
            for (int nt = 0; nt < 16; nt++) {
                acc[nt][0] *= sc0; acc[nt][1] *= sc0;
                acc[nt][2] *= sc1; acc[nt][3] *= sc1;
            }
        }

        // ---- pack P into A-fragments (S-frag layout == A-frag layout)
        unsigned pa[4][4];
#pragma unroll
        for (int kt = 0; kt < 4; kt++) {
            pa[kt][0] = h2u(__floats2half2_rn(sf[2 * kt][0],     sf[2 * kt][1]));
            pa[kt][1] = h2u(__floats2half2_rn(sf[2 * kt][2],     sf[2 * kt][3]));
            pa[kt][2] = h2u(__floats2half2_rn(sf[2 * kt + 1][0], sf[2 * kt + 1][1]));
            pa[kt][3] = h2u(__floats2half2_rn(sf[2 * kt + 1][2], sf[2 * kt + 1][3]));
        }

        // ---- acc += P V  (ldmatrix.x4.trans for V B-fragments)
#pragma unroll
        for (int kt = 0; kt < 4; kt++) {
#pragma unroll
            for (int np = 0; np < 8; np++) {
                unsigned b0, b1, b2, b3;
                unsigned addr = su(&S->Vs[bufi][kt * 16 + (lane & 15)]
                                         [c0 + np * 16 + (lane >> 4) * 8]);
                LDSM_X4T(b0, b1, b2, b3, addr);
                mma16(acc[2 * np],     pa[kt], b0, b1);
                mma16(acc[2 * np + 1], pa[kt], b2, b3);
            }
        }

        __syncthreads();
        if (t + 2 < NTILES) issue(t + 2);
    }

    // ---- epilogue
    float il0 = 1.0f / l0, il1 = 1.0f / l1;
    float* o0 = out + (rowbase + r0) * (2 * CDIM) + chan0 + z * CDIM + c0;
    float* o1 = o0 + (size_t)8 * (2 * CDIM);
    if (addMode) {
#pragma unroll
        for (int nt = 0; nt < 16; nt++) {
            int c = nt * 8 + 2 * qc;
            o0[c]     += gv * acc[nt][0] * il0;
            o0[c + 1] += gv * acc[nt][1] * il0;
            o1[c]     += gv * acc[nt][2] * il1;
            o1[c + 1] += gv * acc[nt][3] * il1;
        }
    } else {
#pragma unroll
        for (int nt = 0; nt < 16; nt++) {
            int c = nt * 8 + 2 * qc;
            *(float2*)&o0[c] = make_float2(acc[nt][0] * il0, acc[nt][1] * il0);
            *(float2*)&o1[c] = make_float2(acc[nt][2] * il1, acc[nt][3] * il1);
        }
    }
}

// ---------------------------------------------------------------------------
// Launcher
// ---------------------------------------------------------------------------
extern "C" void kernel_launch(void* const* d_in, const int* in_sizes, int n_in,
                              void* d_out, int out_size) {
    const float* x = (const float*)d_in[0];
    const float* w[13];
    for (int i = 1; i <= 12; i++) w[i] = (const float*)d_in[i];
    const float* alpha = (const float*)d_in[13];
    const float* gamma = (const float*)d_in[14];
    float* out = (float*)d_out;

    float *ecg, *pcg, *qk; __half *vh, *khi, *klo;
    cudaGetSymbolAddress((void**)&ecg, g_ecg);
    cudaGetSymbolAddress((void**)&pcg, g_pcg);
    cudaGetSymbolAddress((void**)&qk,  g_QK);
    cudaGetSymbolAddress((void**)&vh,  g_Vh);
    cudaGetSymbolAddress((void**)&khi, g_Khi);
    cudaGetSymbolAddress((void**)&klo, g_Klo);

    auto QK = [&](int a) { return qk  + (size_t)a * MROWS * 64; };
    auto KH = [&](int a) { return khi + (size_t)a * MROWS * 32; };
    auto KL = [&](int a) { return klo + (size_t)a * MROWS * 32; };
    auto VH = [&](int a) { return vh  + (size_t)a * MROWS * CDIM; };

    cudaFuncSetAttribute(attn16, cudaFuncAttributeMaxDynamicSharedMemorySize,
                         (int)sizeof(ASmem));

    // 1) de-interleave
    split_kernel<<<(MROWS * CDIM + 255) / 256, 256>>>((const float2*)x, ecg, pcg);

    // 2) projections
    dim3 gQ(1, MROWS / 128);
    dim3 gV(CDIM / 64, MROWS / 128);
    // QK(0) = ecg@[w4|w11] = [Q0 | K1] -> K half 1 feeds attn z=1
    proj_qk3<<<gQ, 256>>>(ecg, w[4], w[11], QK(0), KH(1), KL(1), 1, nullptr);
    // QK(1) = pcg@[w5|w10] = [K0 | Q1] -> K half 0 feeds attn z=0
    proj_qk3<<<gQ, 256>>>(pcg, w[5], w[10], QK(1), KH(0), KL(0), 0, nullptr);
    // intra:  [Q2|K2], [Q3|K3] -> K half 1
    proj_qk3<<<gQ, 256>>>(ecg, w[1], w[2],  QK(2), KH(2), KL(2), 1, alpha);
    proj_qk3<<<gQ, 256>>>(pcg, w[7], w[8],  QK(3), KH(3), KL(3), 1, gamma);
    // V projections (fp16 mma, fp16 out)
    proj_v<<<gV, 256>>>(pcg, w[6],  VH(0), nullptr);
    proj_v<<<gV, 256>>>(ecg, w[12], VH(1), nullptr);
    proj_v<<<gV, 256>>>(ecg, w[3],  VH(2), alpha);
    proj_v<<<gV, 256>>>(pcg, w[9],  VH(3), gamma);

    // 3) attention: both ungated paths in one launch (z = 0,1)
    size_t smem = sizeof(ASmem);
    AttnArgs ap{};
    ap.Q[0] = QK(0);      ap.Khi[0] = KH(0); ap.Klo[0] = KL(0); ap.V[0] = VH(0);
    ap.Q[1] = QK(1) + 32; ap.Khi[1] = KH(1); ap.Klo[1] = KL(1); ap.V[1] = VH(1);
    attn16<<<dim3(LSEQ / 64, NBATCH, 2), 256, smem>>>(ap, out, nullptr, 0, 0);

    // gated intra paths
    AttnArgs a2{};
    a2.Q[0] = QK(2); a2.Khi[0] = KH(2); a2.Klo[0] = KL(2); a2.V[0] = VH(2);
    attn16<<<dim3(LSEQ / 64, NBATCH, 1), 256, smem>>>(a2, out, alpha, 1, 0);
    AttnArgs a3{};
    a3.Q[0] = QK(3); a3.Khi[0] = KH(3); a3.Klo[0] = KL(3); a3.V[0] = VH(3);
    attn16<<<dim3(LSEQ / 64, NBATCH, 1), 256, smem>>>(a3, out, gamma, 1, CDIM);
}